// round 14
// baseline (speedup 1.0000x reference)
#include <cuda_runtime.h>
#include <cuda_fp16.h>
#include <math.h>
#include <stdint.h>

#define B_  4
#define T_  2048
#define C_  1024
#define H_  16
#define HD_ 64
#define M_  (B_*T_)   // 8192

// fp16 scratch (allocation-free)
__device__ __half g_xh[M_*C_];
__device__ __half g_wqT[H_*HD_*C_], g_wkT[H_*HD_*C_], g_wvT[H_*HD_*C_];
__device__ __half g_wpT[C_*C_];
__device__ __half g_qh[M_*C_], g_kh[M_*C_], g_vh[M_*C_];
__device__ __half g_oh[M_*C_];
__device__ float  g_bias[3*H_*HD_];

// ---------------------------------------------------------------------------
// helpers
// ---------------------------------------------------------------------------
__device__ __forceinline__ uint32_t smem_u32(const void* p){
    uint32_t a;
    asm("{ .reg .u64 t; cvta.to.shared.u64 t, %1; cvt.u32.u64 %0, t; }"
        : "=r"(a) : "l"(p));
    return a;
}
__device__ __forceinline__ void ldsm_x4(uint32_t* r, uint32_t addr){
    asm volatile("ldmatrix.sync.aligned.m8n8.x4.shared.b16 {%0,%1,%2,%3}, [%4];"
        : "=r"(r[0]), "=r"(r[1]), "=r"(r[2]), "=r"(r[3]) : "r"(addr));
}
__device__ __forceinline__ void ldsm_x4t(uint32_t* r, uint32_t addr){
    asm volatile("ldmatrix.sync.aligned.m8n8.x4.trans.shared.b16 {%0,%1,%2,%3}, [%4];"
        : "=r"(r[0]), "=r"(r[1]), "=r"(r[2]), "=r"(r[3]) : "r"(addr));
}
__device__ __forceinline__ void mma16816(float* c, const uint32_t* a, const uint32_t* b){
    asm volatile(
        "mma.sync.aligned.m16n8k16.row.col.f32.f16.f16.f32 "
        "{%0,%1,%2,%3}, {%4,%5,%6,%7}, {%8,%9}, {%0,%1,%2,%3};"
        : "+f"(c[0]), "+f"(c[1]), "+f"(c[2]), "+f"(c[3])
        : "r"(a[0]), "r"(a[1]), "r"(a[2]), "r"(a[3]), "r"(b[0]), "r"(b[1]));
}
__device__ __forceinline__ void cp16(uint32_t dst, const void* src){
    asm volatile("cp.async.cg.shared.global [%0], [%1], 16;" :: "r"(dst), "l"(src));
}
#define CP_COMMIT() asm volatile("cp.async.commit_group;" ::: "memory")
#define CP_WAIT1()  asm volatile("cp.async.wait_group 1;" ::: "memory")

__device__ __forceinline__ uint32_t pack_h(float a, float b){
    __half2 hp = __floats2half2_rn(a, b);
    return *(uint32_t*)&hp;
}

// ---------------------------------------------------------------------------
// Prologue kernels
// ---------------------------------------------------------------------------
__global__ __launch_bounds__(256) void conv_x(const float* __restrict__ x){
    int i = (blockIdx.x*256 + threadIdx.x) * 4;
    float4 a = *(const float4*)(x + i);
    uint2 hi;
    hi.x = pack_h(a.x, a.y);
    hi.y = pack_h(a.z, a.w);
    *(uint2*)&g_xh[i] = hi;
}

__global__ __launch_bounds__(256) void conv_w(
    const float* __restrict__ Wq, const float* __restrict__ Wk,
    const float* __restrict__ Wv, const float* __restrict__ Wp)
{
    int idx = blockIdx.x*256 + threadIdx.x;           // 0 .. 4M-1
    int which = idx >> 20;
    int o = idx & 0xFFFFF;
    if (which < 3) {
        const float* W = (which == 0) ? Wq : (which == 1) ? Wk : Wv;
        __half* wT = (which == 0) ? g_wqT : (which == 1) ? g_wkT : g_wvT;
        int c = o & (C_-1);
        int d = (o >> 10) & 63;
        int h = o >> 16;
        wT[o] = __float2half_rn(W[((size_t)h*C_ + c)*HD_ + d]);
    } else {
        int k = o & (C_-1);
        int n = o >> 10;
        g_wpT[o] = __float2half_rn(Wp[(size_t)k*C_ + n]);
    }
}

__global__ void stage_bias(const float* bq, const float* bk, const float* bv){
    int i = threadIdx.x + blockIdx.x*256;
    if (i < H_*HD_) {
        g_bias[i] = bq[i];
        g_bias[H_*HD_ + i] = bk[i];
        g_bias[2*H_*HD_ + i] = bv[i];
    }
}

// ---------------------------------------------------------------------------
// GEMM mma chunk: BK=64, single fp16 pass, paired-x4 B loads.
// ---------------------------------------------------------------------------
#define BK  64
#define SK  72                    // 64 halves + 8 pad
#define TILE_H (128*SK)           // 9216 halves
#define STAGE_H (2*TILE_H)        // A|B
#define GEMM_SMEM (3*STAGE_H*2)   // 110592 B

__device__ __forceinline__ void gemm_mma_chunk(
    uint32_t st, uint32_t aoff, int wn, int lane, float acc[4][4][4])
{
    uint32_t sA = st, sB = st + TILE_H*2;
    int g01 = (lane >> 4) << 3;
    int gk  = ((lane >> 3) & 1) << 3;
    int l7  = lane & 7;

    #pragma unroll
    for (int ks = 0; ks < 4; ks++) {
        uint32_t bf[4][2];
        #pragma unroll
        for (int ntp = 0; ntp < 2; ntp++) {
            uint32_t tmp[4];
            uint32_t addr = sB + (((uint32_t)(wn*32 + ntp*16 + g01 + l7))*SK
                                  + ks*16 + gk)*2;
            ldsm_x4(tmp, addr);
            bf[2*ntp][0] = tmp[0]; bf[2*ntp][1] = tmp[1];
            bf[2*ntp+1][0] = tmp[2]; bf[2*ntp+1][1] = tmp[3];
        }
        uint32_t af[4][4];
        #pragma unroll
        for (int mt = 0; mt < 4; mt++)
            ldsm_x4(af[mt], sA + aoff + (mt*16*SK + ks*16)*2);
        #pragma unroll
        for (int mt = 0; mt < 4; mt++)
            #pragma unroll
            for (int nt = 0; nt < 4; nt++)
                mma16816(acc[mt][nt], af[mt], bf[nt]);
    }
}

// ---------------------------------------------------------------------------
// Kernel 1: QKV projection — BK=64, 3-stage, single-pass fp16.
// ---------------------------------------------------------------------------
__global__ __launch_bounds__(256) void qkv_mma()
{
    extern __shared__ __half dynsm[];
    int tid = threadIdx.x, wid = tid >> 5, lane = tid & 31;
    int wm = wid >> 2, wn = wid & 3;
    int mt_ = blockIdx.x, nt_ = blockIdx.y;
    int which = nt_ >> 3, hbase = (nt_ & 7) * 2;
    const int m0 = mt_ * 128;

    const __half* wT = (which == 0) ? g_wqT : (which == 1) ? g_wkT : g_wvT;
    __half* outp = (which == 0) ? g_qh : (which == 1) ? g_kh : g_vh;
    uint32_t sbase = smem_u32(dynsm);
    uint32_t aoff = ((wm*64 + (lane & 15)) * SK + ((lane >> 4) << 3)) * 2;

    float acc[4][4][4] = {};

    auto fill = [&](int stage, int kc) {
        uint32_t st = sbase + stage*STAGE_H*2;
        int k0 = kc * BK;
        #pragma unroll
        for (int it = 0; it < 8; it++) {
            int part = it >> 2;
            int idx = ((it & 3) << 8) + tid;
            int row = idx >> 3, seg = (idx & 7) << 3;
            if (part == 0) {
                cp16(st + (row*SK + seg)*2,
                     g_xh + (size_t)(m0 + row)*C_ + k0 + seg);
            } else {
                int h = hbase + (row >> 6), d = row & 63;
                cp16(st + (TILE_H + row*SK + seg)*2,
                     wT + ((size_t)h*HD_ + d)*C_ + k0 + seg);
            }
        }
    };

    fill(0, 0); CP_COMMIT();
    fill(1, 1); CP_COMMIT();

    for (int kc = 0; kc < 16; kc++) {
        CP_WAIT1();
        __syncthreads();
        if (kc + 2 < 16) fill((kc + 2) % 3, kc + 2);
        CP_COMMIT();
        gemm_mma_chunk(sbase + (kc % 3)*STAGE_H*2, aoff, wn, lane, acc);
    }

    #pragma unroll
    for (int mt = 0; mt < 4; mt++) {
        int mrow = m0 + wm*64 + mt*16 + (lane >> 2);
        #pragma unroll
        for (int half = 0; half < 2; half++) {
            int m = mrow + half*8;
            int b_ = m >> 11, t = m & (T_-1);
            #pragma unroll
            for (int nt = 0; nt < 4; nt++) {
                int n = wn*32 + nt*8 + ((lane & 3) << 1);
                int h = hbase + (n >> 6), d = n & 63;
                size_t off = (((size_t)(b_*H_ + h))*T_ + t)*HD_ + d;
                float c0 = acc[mt][nt][half*2+0] + g_bias[(which*H_ + h)*HD_ + d];
                float c1 = acc[mt][nt][half*2+1] + g_bias[(which*H_ + h)*HD_ + d + 1];
                *(uint32_t*)&outp[off] = pack_h(c0, c1);
            }
        }
    }
}

// ---------------------------------------------------------------------------
// Kernel 2: attention — 128-key smem tiles, one sync per 128 keys,
//           two 64-key compute subtiles per region.
// ---------------------------------------------------------------------------
#define SKA 72
#define KT  128
#define ATILE_H (KT*SKA)           // 9216 halves
#define ASTAGE_H (2*ATILE_H)       // K|V
#define ATTN_SMEM (3*ASTAGE_H*2)   // 110592 B

__global__ __launch_bounds__(256) void attn_mma()
{
    extern __shared__ __half asm_[];
    int tid = threadIdx.x, wid = tid >> 5, lane = tid & 31;
    int qt = 15 - blockIdx.x;
    int bh = blockIdx.y;
    const __half* Qh = g_qh + (size_t)bh * T_ * HD_;
    const __half* Kh = g_kh + (size_t)bh * T_ * HD_;
    const __half* Vh = g_vh + (size_t)bh * T_ * HD_;

    uint32_t sbase = smem_u32(asm_);
    int r0 = lane >> 2, c0 = (lane & 3) << 1;
    int wrow = qt*128 + wid*16;
    int row0 = wrow + r0;
    int g01 = (lane >> 4) << 3;
    int gk  = ((lane >> 3) & 1) << 3;
    int l7  = lane & 7;

    uint32_t qh[4][4];
    #pragma unroll
    for (int ks = 0; ks < 4; ks++) {
        #pragma unroll
        for (int p = 0; p < 4; p++) {
            int rr = row0 + ((p & 1) << 3);
            int cc = ks*16 + c0 + ((p >> 1) << 3);
            qh[ks][p] = *(const uint32_t*)&Qh[(size_t)rr*HD_ + cc];
        }
    }

    float o[8][4];
    #pragma unroll
    for (int i = 0; i < 8; i++) { o[i][0]=o[i][1]=o[i][2]=o[i][3]=0.f; }
    float m_i[2] = {-1e30f, -1e30f}, l_i[2] = {0.f, 0.f};
    const int jmaxT = qt;   // 128-key tiles 0..qt

    auto fill = [&](int stage, int jj) {
        uint32_t st = sbase + stage*ASTAGE_H*2;
        int s0 = jj * KT;
        #pragma unroll
        for (int it = 0; it < 8; it++) {
            int part = it >> 2;
            int idx = ((it & 3) << 8) + tid;
            int row = idx >> 3, seg = (idx & 7) << 3;
            if (part == 0)
                cp16(st + (row*SKA + seg)*2, Kh + (size_t)(s0 + row)*HD_ + seg);
            else
                cp16(st + (ATILE_H + row*SKA + seg)*2, Vh + (size_t)(s0 + row)*HD_ + seg);
        }
    };

    fill(0, 0); CP_COMMIT();
    if (jmaxT >= 1) fill(1, 1);
    CP_COMMIT();   // empty group if qt == 0; in-order retirement keeps WAIT1 correct

    for (int jj = 0; jj <= jmaxT; jj++) {
        CP_WAIT1();
        __syncthreads();
        if (jj + 2 <= jmaxT) fill((jj + 2) % 3, jj + 2);
        CP_COMMIT();

        uint32_t st = sbase + (jj % 3)*ASTAGE_H*2;
        uint32_t sK = st, sV = st + ATILE_H*2;

        #pragma unroll
        for (int sub = 0; sub < 2; sub++) {
            int s0g = jj*KT + sub*64;          // global first key of subtile
            if (s0g > wrow + 15) continue;     // fully above diagonal for this warp
            int sr = sub*64;                   // row offset inside smem tile

            // S = Q K^T (single pass, paired-x4 K loads)
            float c[8][4] = {};
            #pragma unroll
            for (int ks = 0; ks < 4; ks++) {
                uint32_t bf[8][2];
                #pragma unroll
                for (int ntp = 0; ntp < 4; ntp++) {
                    uint32_t tmp[4];
                    uint32_t addr = sK + (((uint32_t)(sr + ntp*16 + g01 + l7))*SKA
                                          + ks*16 + gk)*2;
                    ldsm_x4(tmp, addr);
                    bf[2*ntp][0] = tmp[0]; bf[2*ntp][1] = tmp[1];
                    bf[2*ntp+1][0] = tmp[2]; bf[2*ntp+1][1] = tmp[3];
                }
                #pragma unroll
                for (int nt = 0; nt < 8; nt++)
                    mma16816(c[nt], qh[ks], bf[nt]);
            }
            // scale + causal mask
            bool dflag = (s0g + 63) > wrow;
            #pragma unroll
            for (int nt = 0; nt < 8; nt++) {
                #pragma unroll
                for (int e = 0; e < 4; e++) {
                    float s = c[nt][e] * 0.03125f;
                    if (dflag) {
                        int col = s0g + nt*8 + c0 + (e & 1);
                        int row = row0 + ((e >> 1) << 3);
                        if (col > row) s = -1e30f;
                    }
                    c[nt][e] = s;
                }
            }
            // online softmax
            #pragma unroll
            for (int r = 0; r < 2; r++) {
                float mx = -1e30f;
                #pragma unroll
                for (int nt = 0; nt < 8; nt++)
                    mx = fmaxf(mx, fmaxf(c[nt][2*r], c[nt][2*r+1]));
                mx = fmaxf(mx, __shfl_xor_sync(0xffffffffu, mx, 1));
                mx = fmaxf(mx, __shfl_xor_sync(0xffffffffu, mx, 2));
                float mnew = fmaxf(m_i[r], mx);
                float alpha = __expf(m_i[r] - mnew);
                m_i[r] = mnew;
                float rs = 0.f;
                #pragma unroll
                for (int nt = 0; nt < 8; nt++) {
                    float p0 = __expf(c[nt][2*r]   - mnew);
                    float p1 = __expf(c[nt][2*r+1] - mnew);
                    c[nt][2*r] = p0; c[nt][2*r+1] = p1;
                    rs += p0 + p1;
                }
                rs += __shfl_xor_sync(0xffffffffu, rs, 1);
                rs += __shfl_xor_sync(0xffffffffu, rs, 2);
                l_i[r] = l_i[r]*alpha + rs;
                #pragma unroll
                for (int nt = 0; nt < 8; nt++) {
                    o[nt][2*r]   *= alpha;
                    o[nt][2*r+1] *= alpha;
                }
            }
            // O += P V (single pass, paired-x4 trans V loads)
            #pragma unroll
            for (int ks = 0; ks < 4; ks++) {
                uint32_t ph[4];
                ph[0] = pack_h(c[2*ks][0],   c[2*ks][1]);
                ph[1] = pack_h(c[2*ks][2],   c[2*ks][3]);
                ph[2] = pack_h(c[2*ks+1][0], c[2*ks+1][1]);
                ph[3] = pack_h(c[2*ks+1][2], c[2*ks+1][3]);
                uint32_t bv[8][2];
                #pragma unroll
                for (int ntp = 0; ntp < 4; ntp++) {
                    uint32_t tmp[4];
                    uint32_t addr = sV + (((uint32_t)(sr + ks*16 + gk + l7))*SKA
                                          + ntp*16 + g01)*2;
                    ldsm_x4t(tmp, addr);
                    bv[2*ntp][0] = tmp[0]; bv[2*ntp][1] = tmp[1];
                    bv[2*ntp+1][0] = tmp[2]; bv[2*ntp+1][1] = tmp[3];
                }
                #pragma unroll
                for (int nt = 0; nt < 8; nt++)
                    mma16816(o[nt], ph, bv[nt]);
            }
        }
        __syncthreads();
    }

    float inv0 = 1.0f / l_i[0], inv1 = 1.0f / l_i[1];
    __half* Oh = g_oh + (size_t)bh * T_ * HD_;
    #pragma unroll
    for (int nt = 0; nt < 8; nt++) {
        int d = nt*8 + c0;
        *(uint32_t*)&Oh[(size_t)row0*HD_ + d]     = pack_h(o[nt][0]*inv0, o[nt][1]*inv0);
        *(uint32_t*)&Oh[(size_t)(row0+8)*HD_ + d] = pack_h(o[nt][2]*inv1, o[nt][3]*inv1);
    }
}

// ---------------------------------------------------------------------------
// Kernel 3: output projection — BK=64, 3-stage, single-pass fp16.
// ---------------------------------------------------------------------------
__global__ __launch_bounds__(256) void proj_mma(
    const float* __restrict__ bp, float* __restrict__ outp)
{
    extern __shared__ __half dynsm[];
    int tid = threadIdx.x, wid = tid >> 5, lane = tid & 31;
    int wm = wid >> 2, wn = wid & 3;
    const int m0 = blockIdx.x * 128, n0 = blockIdx.y * 128;

    uint32_t sbase = smem_u32(dynsm);
    uint32_t aoff = ((wm*64 + (lane & 15)) * SK + ((lane >> 4) << 3)) * 2;

    float acc[4][4][4] = {};

    auto fill = [&](int stage, int kc) {
        uint32_t st = sbase + stage*STAGE_H*2;
        int k0 = kc * BK;
        int h = k0 >> 6;
        #pragma unroll
        for (int it = 0; it < 8; it++) {
            int part = it >> 2;
            int idx = ((it & 3) << 8) + tid;
            int row = idx >> 3, seg = (idx & 7) << 3;
            if (part == 0) {
                int m = m0 + row, b_ = m >> 11, t = m & (T_-1);
                cp16(st + (row*SK + seg)*2,
                     g_oh + (((size_t)(b_*H_ + h))*T_ + t)*HD_ + seg);
            } else {
                cp16(st + (TILE_H + row*SK + seg)*2,
                     g_wpT + (size_t)(n0 + row)*C_ + k0 + seg);
            }
        }
    };

    fill(0, 0); CP_COMMIT();
    fill(1, 1); CP_COMMIT();

    for (int kc = 0; kc < 16; kc++) {
        CP_WAIT1();
        __syncthreads();
        if (kc + 2 < 16) fill((kc + 2) % 3, kc + 2);
        CP_COMMIT();
        gemm_mma_chunk(sbase + (kc % 3)*STAGE_H*2, aoff, wn, lane, acc);
    }

    #pragma unroll
    for (int mt = 0; mt < 4; mt++) {
        int mrow = m0 + wm*64 + mt*16 + (lane >> 2);
        #pragma unroll
        for (int half = 0; half < 2; half++) {
            int m = mrow + half*8;
            #pragma unroll
            for (int nt = 0; nt < 4; nt++) {
                int n = wn*32 + nt*8 + ((lane & 3) << 1);
                float c0 = acc[mt][nt][half*2+0] + bp[n0 + n];
                float c1 = acc[mt][nt][half*2+1] + bp[n0 + n + 1];
                *(float2*)&outp[(size_t)m*C_ + n0 + n] = make_float2(c0, c1);
            }
        }
    }
}

// ---------------------------------------------------------------------------
extern "C" void kernel_launch(void* const* d_in, const int* in_sizes, int n_in,
                              void* d_out, int out_size)
{
    const float* x  = (const float*)d_in[0];
    const float* Wq = (const float*)d_in[1];
    const float* bq = (const float*)d_in[2];
    const float* Wk = (const float*)d_in[3];
    const float* bk = (const float*)d_in[4];
    const float* Wv = (const float*)d_in[5];
    const float* bv = (const float*)d_in[6];
    const float* Wp = (const float*)d_in[7];
    const float* bp = (const float*)d_in[8];
    float* out = (float*)d_out;

    cudaFuncSetAttribute(qkv_mma,  cudaFuncAttributeMaxDynamicSharedMemorySize, GEMM_SMEM);
    cudaFuncSetAttribute(proj_mma, cudaFuncAttributeMaxDynamicSharedMemorySize, GEMM_SMEM);
    cudaFuncSetAttribute(attn_mma, cudaFuncAttributeMaxDynamicSharedMemorySize, ATTN_SMEM);

    conv_x<<<M_*C_/4/256, 256>>>(x);
    conv_w<<<4*1048576/256, 256>>>(Wq, Wk, Wv, Wp);
    stage_bias<<<4, 256>>>(bq, bk, bv);
    qkv_mma<<<dim3(64, 24), 256, GEMM_SMEM>>>();
    attn_mma<<<dim3(16, 64), 256, ATTN_SMEM>>>();
    proj_mma<<<dim3(64, 8), 256, GEMM_SMEM>>>(bp, out);
}

// round 15
// speedup vs baseline: 1.0514x; 1.0514x over previous
#include <cuda_runtime.h>
#include <cuda_fp16.h>
#include <math.h>
#include <stdint.h>

#define B_  4
#define T_  2048
#define C_  1024
#define H_  16
#define HD_ 64
#define M_  (B_*T_)   // 8192

// fp16 scratch (allocation-free)
__device__ __half g_xh[M_*C_];
__device__ __half g_wqT[H_*HD_*C_], g_wkT[H_*HD_*C_], g_wvT[H_*HD_*C_];
__device__ __half g_wpT[C_*C_];
__device__ __half g_qh[M_*C_], g_kh[M_*C_], g_vh[M_*C_];
__device__ __half g_oh[M_*C_];
__device__ float  g_bias[3*H_*HD_];

// ---------------------------------------------------------------------------
// helpers
// ---------------------------------------------------------------------------
__device__ __forceinline__ uint32_t smem_u32(const void* p){
    uint32_t a;
    asm("{ .reg .u64 t; cvta.to.shared.u64 t, %1; cvt.u32.u64 %0, t; }"
        : "=r"(a) : "l"(p));
    return a;
}
__device__ __forceinline__ void ldsm_x4(uint32_t* r, uint32_t addr){
    asm volatile("ldmatrix.sync.aligned.m8n8.x4.shared.b16 {%0,%1,%2,%3}, [%4];"
        : "=r"(r[0]), "=r"(r[1]), "=r"(r[2]), "=r"(r[3]) : "r"(addr));
}
__device__ __forceinline__ void ldsm_x4t(uint32_t* r, uint32_t addr){
    asm volatile("ldmatrix.sync.aligned.m8n8.x4.trans.shared.b16 {%0,%1,%2,%3}, [%4];"
        : "=r"(r[0]), "=r"(r[1]), "=r"(r[2]), "=r"(r[3]) : "r"(addr));
}
__device__ __forceinline__ void mma16816(float* c, const uint32_t* a, const uint32_t* b){
    asm volatile(
        "mma.sync.aligned.m16n8k16.row.col.f32.f16.f16.f32 "
        "{%0,%1,%2,%3}, {%4,%5,%6,%7}, {%8,%9}, {%0,%1,%2,%3};"
        : "+f"(c[0]), "+f"(c[1]), "+f"(c[2]), "+f"(c[3])
        : "r"(a[0]), "r"(a[1]), "r"(a[2]), "r"(a[3]), "r"(b[0]), "r"(b[1]));
}
__device__ __forceinline__ void cp16(uint32_t dst, const void* src){
    asm volatile("cp.async.cg.shared.global [%0], [%1], 16;" :: "r"(dst), "l"(src));
}
#define CP_COMMIT() asm volatile("cp.async.commit_group;" ::: "memory")
#define CP_WAIT1()  asm volatile("cp.async.wait_group 1;" ::: "memory")

__device__ __forceinline__ uint32_t pack_h(float a, float b){
    __half2 hp = __floats2half2_rn(a, b);
    return *(uint32_t*)&hp;
}

// ---------------------------------------------------------------------------
// Prologue kernel 1: x -> fp16, + bias staging (blocks 0-3)
// ---------------------------------------------------------------------------
__global__ __launch_bounds__(256) void conv_x(
    const float* __restrict__ x,
    const float* __restrict__ bq, const float* __restrict__ bk,
    const float* __restrict__ bv)
{
    int gidx = blockIdx.x*256 + threadIdx.x;
    int i = gidx * 4;
    float4 a = *(const float4*)(x + i);
    uint2 hi;
    hi.x = pack_h(a.x, a.y);
    hi.y = pack_h(a.z, a.w);
    *(uint2*)&g_xh[i] = hi;
    if (gidx < H_*HD_) {
        g_bias[gidx]            = bq[gidx];
        g_bias[H_*HD_ + gidx]   = bk[gidx];
        g_bias[2*H_*HD_ + gidx] = bv[gidx];
    }
}

// ---------------------------------------------------------------------------
// Prologue kernel 2: coalesced weight transpose via 32x32 smem tiles.
//  blocks 0..3071:  QKV  W[h][c][d] -> wT[h][d][c]   (3 mats x 16 h x 64 tiles)
//  blocks 3072..4095: Wp [k][n] -> wpT[n][k]          (1024 tiles)
// ---------------------------------------------------------------------------
__global__ __launch_bounds__(256) void conv_wT(
    const float* __restrict__ Wq, const float* __restrict__ Wk,
    const float* __restrict__ Wv, const float* __restrict__ Wp)
{
    __shared__ float ts[32][33];
    int tx = threadIdx.x & 31, ty = threadIdx.x >> 5;   // 32 x 8
    int bid = blockIdx.x;

    if (bid < 3072) {
        int which = bid >> 10;
        int r = bid & 1023;
        int h = r >> 6;
        int t = r & 63;
        int c0 = (t >> 1) << 5;      // 32 c-tiles
        int d0 = (t & 1) << 5;       // 2 d-tiles
        const float* W = (which == 0) ? Wq : (which == 1) ? Wk : Wv;
        __half* wT = (which == 0) ? g_wqT : (which == 1) ? g_wkT : g_wvT;
        #pragma unroll
        for (int i = 0; i < 4; i++) {
            int c = c0 + ty + i*8;
            ts[ty + i*8][tx] = W[((size_t)h*C_ + c)*HD_ + d0 + tx];
        }
        __syncthreads();
        #pragma unroll
        for (int i = 0; i < 4; i++) {
            int d = d0 + ty + i*8;
            wT[((size_t)h*HD_ + d)*C_ + c0 + tx] = __float2half_rn(ts[tx][ty + i*8]);
        }
    } else {
        int r = bid - 3072;
        int k0 = (r >> 5) << 5, n0 = (r & 31) << 5;
        #pragma unroll
        for (int i = 0; i < 4; i++) {
            int k = k0 + ty + i*8;
            ts[ty + i*8][tx] = Wp[(size_t)k*C_ + n0 + tx];
        }
        __syncthreads();
        #pragma unroll
        for (int i = 0; i < 4; i++) {
            int n = n0 + ty + i*8;
            g_wpT[(size_t)n*C_ + k0 + tx] = __float2half_rn(ts[tx][ty + i*8]);
        }
    }
}

// ---------------------------------------------------------------------------
// GEMM mma chunk: BK=64, single fp16 pass, paired-x4 B loads.
// ---------------------------------------------------------------------------
#define BK  64
#define SK  72                    // 64 halves + 8 pad
#define TILE_H (128*SK)           // 9216 halves
#define STAGE_H (2*TILE_H)        // A|B
#define GEMM_SMEM (3*STAGE_H*2)   // 110592 B

__device__ __forceinline__ void gemm_mma_chunk(
    uint32_t st, uint32_t aoff, int wn, int lane, float acc[4][4][4])
{
    uint32_t sA = st, sB = st + TILE_H*2;
    int g01 = (lane >> 4) << 3;
    int gk  = ((lane >> 3) & 1) << 3;
    int l7  = lane & 7;

    #pragma unroll
    for (int ks = 0; ks < 4; ks++) {
        uint32_t bf[4][2];
        #pragma unroll
        for (int ntp = 0; ntp < 2; ntp++) {
            uint32_t tmp[4];
            uint32_t addr = sB + (((uint32_t)(wn*32 + ntp*16 + g01 + l7))*SK
                                  + ks*16 + gk)*2;
            ldsm_x4(tmp, addr);
            bf[2*ntp][0] = tmp[0]; bf[2*ntp][1] = tmp[1];
            bf[2*ntp+1][0] = tmp[2]; bf[2*ntp+1][1] = tmp[3];
        }
        uint32_t af[4][4];
        #pragma unroll
        for (int mt = 0; mt < 4; mt++)
            ldsm_x4(af[mt], sA + aoff + (mt*16*SK + ks*16)*2);
        #pragma unroll
        for (int mt = 0; mt < 4; mt++)
            #pragma unroll
            for (int nt = 0; nt < 4; nt++)
                mma16816(acc[mt][nt], af[mt], bf[nt]);
    }
}

// ---------------------------------------------------------------------------
// Kernel 1: QKV projection — BK=64, 3-stage, single-pass fp16.
// ---------------------------------------------------------------------------
__global__ __launch_bounds__(256) void qkv_mma()
{
    extern __shared__ __half dynsm[];
    int tid = threadIdx.x, wid = tid >> 5, lane = tid & 31;
    int wm = wid >> 2, wn = wid & 3;
    int mt_ = blockIdx.x, nt_ = blockIdx.y;
    int which = nt_ >> 3, hbase = (nt_ & 7) * 2;
    const int m0 = mt_ * 128;

    const __half* wT = (which == 0) ? g_wqT : (which == 1) ? g_wkT : g_wvT;
    __half* outp = (which == 0) ? g_qh : (which == 1) ? g_kh : g_vh;
    uint32_t sbase = smem_u32(dynsm);
    uint32_t aoff = ((wm*64 + (lane & 15)) * SK + ((lane >> 4) << 3)) * 2;

    float acc[4][4][4] = {};

    auto fill = [&](int stage, int kc) {
        uint32_t st = sbase + stage*STAGE_H*2;
        int k0 = kc * BK;
        #pragma unroll
        for (int it = 0; it < 8; it++) {
            int part = it >> 2;
            int idx = ((it & 3) << 8) + tid;
            int row = idx >> 3, seg = (idx & 7) << 3;
            if (part == 0) {
                cp16(st + (row*SK + seg)*2,
                     g_xh + (size_t)(m0 + row)*C_ + k0 + seg);
            } else {
                int h = hbase + (row >> 6), d = row & 63;
                cp16(st + (TILE_H + row*SK + seg)*2,
                     wT + ((size_t)h*HD_ + d)*C_ + k0 + seg);
            }
        }
    };

    fill(0, 0); CP_COMMIT();
    fill(1, 1); CP_COMMIT();

    for (int kc = 0; kc < 16; kc++) {
        CP_WAIT1();
        __syncthreads();
        if (kc + 2 < 16) fill((kc + 2) % 3, kc + 2);
        CP_COMMIT();
        gemm_mma_chunk(sbase + (kc % 3)*STAGE_H*2, aoff, wn, lane, acc);
    }

    #pragma unroll
    for (int mt = 0; mt < 4; mt++) {
        int mrow = m0 + wm*64 + mt*16 + (lane >> 2);
        #pragma unroll
        for (int half = 0; half < 2; half++) {
            int m = mrow + half*8;
            int b_ = m >> 11, t = m & (T_-1);
            #pragma unroll
            for (int nt = 0; nt < 4; nt++) {
                int n = wn*32 + nt*8 + ((lane & 3) << 1);
                int h = hbase + (n >> 6), d = n & 63;
                size_t off = (((size_t)(b_*H_ + h))*T_ + t)*HD_ + d;
                float c0 = acc[mt][nt][half*2+0] + g_bias[(which*H_ + h)*HD_ + d];
                float c1 = acc[mt][nt][half*2+1] + g_bias[(which*H_ + h)*HD_ + d + 1];
                *(uint32_t*)&outp[off] = pack_h(c0, c1);
            }
        }
    }
}

// ---------------------------------------------------------------------------
// Kernel 2: attention — 64-key tiles (R12 proven config).
// ---------------------------------------------------------------------------
#define SKA 72
#define ATILE_H (64*SKA)
#define ASTAGE_H (2*ATILE_H)
#define ATTN_SMEM (3*ASTAGE_H*2)   // 55296 B

__global__ __launch_bounds__(256) void attn_mma()
{
    extern __shared__ __half asm_[];
    int tid = threadIdx.x, wid = tid >> 5, lane = tid & 31;
    int qt = 15 - blockIdx.x;
    int bh = blockIdx.y;
    const __half* Qh = g_qh + (size_t)bh * T_ * HD_;
    const __half* Kh = g_kh + (size_t)bh * T_ * HD_;
    const __half* Vh = g_vh + (size_t)bh * T_ * HD_;

    uint32_t sbase = smem_u32(asm_);
    int r0 = lane >> 2, c0 = (lane & 3) << 1;
    int wrow = qt*128 + wid*16;
    int row0 = wrow + r0;
    int g01 = (lane >> 4) << 3;
    int gk  = ((lane >> 3) & 1) << 3;
    int l7  = lane & 7;

    uint32_t qh[4][4];
    #pragma unroll
    for (int ks = 0; ks < 4; ks++) {
        #pragma unroll
        for (int p = 0; p < 4; p++) {
            int rr = row0 + ((p & 1) << 3);
            int cc = ks*16 + c0 + ((p >> 1) << 3);
            qh[ks][p] = *(const uint32_t*)&Qh[(size_t)rr*HD_ + cc];
        }
    }

    float o[8][4];
    #pragma unroll
    for (int i = 0; i < 8; i++) { o[i][0]=o[i][1]=o[i][2]=o[i][3]=0.f; }
    float m_i[2] = {-1e30f, -1e30f}, l_i[2] = {0.f, 0.f};
    int jmax = 2*qt + 1;

    auto fill = [&](int stage, int j) {
        uint32_t st = sbase + stage*ASTAGE_H*2;
        int s0 = j * 64;
        #pragma unroll
        for (int it = 0; it < 4; it++) {
            int part = it >> 1;
            int idx = ((it & 1) << 8) + tid;
            int row = idx >> 3, seg = (idx & 7) << 3;
            if (part == 0)
                cp16(st + (row*SKA + seg)*2, Kh + (size_t)(s0 + row)*HD_ + seg);
            else
                cp16(st + (ATILE_H + row*SKA + seg)*2, Vh + (size_t)(s0 + row)*HD_ + seg);
        }
    };

    fill(0, 0); CP_COMMIT();
    fill(1, 1); CP_COMMIT();

    for (int j = 0; j <= jmax; j++) {
        CP_WAIT1();
        __syncthreads();
        if (j + 2 <= jmax) fill((j + 2) % 3, j + 2);
        CP_COMMIT();

        bool dead = (j*64) > (wrow + 15);
        if (!dead) {
            uint32_t st = sbase + (j % 3)*ASTAGE_H*2;
            uint32_t sK = st, sV = st + ATILE_H*2;
            float c[8][4] = {};
            #pragma unroll
            for (int ks = 0; ks < 4; ks++) {
                uint32_t bf[8][2];
                #pragma unroll
                for (int ntp = 0; ntp < 4; ntp++) {
                    uint32_t tmp[4];
                    uint32_t addr = sK + (((uint32_t)(ntp*16 + g01 + l7))*SKA
                                          + ks*16 + gk)*2;
                    ldsm_x4(tmp, addr);
                    bf[2*ntp][0] = tmp[0]; bf[2*ntp][1] = tmp[1];
                    bf[2*ntp+1][0] = tmp[2]; bf[2*ntp+1][1] = tmp[3];
                }
                #pragma unroll
                for (int nt = 0; nt < 8; nt++)
                    mma16816(c[nt], qh[ks], bf[nt]);
            }
            bool dflag = (j >= 2*qt);
            #pragma unroll
            for (int nt = 0; nt < 8; nt++) {
                #pragma unroll
                for (int e = 0; e < 4; e++) {
                    float s = c[nt][e] * 0.03125f;
                    if (dflag) {
                        int col = j*64 + nt*8 + c0 + (e & 1);
                        int row = row0 + ((e >> 1) << 3);
                        if (col > row) s = -1e30f;
                    }
                    c[nt][e] = s;
                }
            }
            #pragma unroll
            for (int r = 0; r < 2; r++) {
                float mx = -1e30f;
                #pragma unroll
                for (int nt = 0; nt < 8; nt++)
                    mx = fmaxf(mx, fmaxf(c[nt][2*r], c[nt][2*r+1]));
                mx = fmaxf(mx, __shfl_xor_sync(0xffffffffu, mx, 1));
                mx = fmaxf(mx, __shfl_xor_sync(0xffffffffu, mx, 2));
                float mnew = fmaxf(m_i[r], mx);
                float alpha = __expf(m_i[r] - mnew);
                m_i[r] = mnew;
                float rs = 0.f;
                #pragma unroll
                for (int nt = 0; nt < 8; nt++) {
                    float p0 = __expf(c[nt][2*r]   - mnew);
                    float p1 = __expf(c[nt][2*r+1] - mnew);
                    c[nt][2*r] = p0; c[nt][2*r+1] = p1;
                    rs += p0 + p1;
                }
                rs += __shfl_xor_sync(0xffffffffu, rs, 1);
                rs += __shfl_xor_sync(0xffffffffu, rs, 2);
                l_i[r] = l_i[r]*alpha + rs;
                #pragma unroll
                for (int nt = 0; nt < 8; nt++) {
                    o[nt][2*r]   *= alpha;
                    o[nt][2*r+1] *= alpha;
                }
            }
            #pragma unroll
            for (int ks = 0; ks < 4; ks++) {
                uint32_t ph[4];
                ph[0] = pack_h(c[2*ks][0],   c[2*ks][1]);
                ph[1] = pack_h(c[2*ks][2],   c[2*ks][3]);
                ph[2] = pack_h(c[2*ks+1][0], c[2*ks+1][1]);
                ph[3] = pack_h(c[2*ks+1][2], c[2*ks+1][3]);
                uint32_t bv[8][2];
                #pragma unroll
                for (int ntp = 0; ntp < 4; ntp++) {
                    uint32_t tmp[4];
                    uint32_t addr = sV + (((uint32_t)(ks*16 + gk + l7))*SKA
                                          + ntp*16 + g01)*2;
                    ldsm_x4t(tmp, addr);
                    bv[2*ntp][0] = tmp[0]; bv[2*ntp][1] = tmp[1];
                    bv[2*ntp+1][0] = tmp[2]; bv[2*ntp+1][1] = tmp[3];
                }
                #pragma unroll
                for (int nt = 0; nt < 8; nt++)
                    mma16816(o[nt], ph, bv[nt]);
            }
        }
        __syncthreads();
    }

    float inv0 = 1.0f / l_i[0], inv1 = 1.0f / l_i[1];
    __half* Oh = g_oh + (size_t)bh * T_ * HD_;
    #pragma unroll
    for (int nt = 0; nt < 8; nt++) {
        int d = nt*8 + c0;
        *(uint32_t*)&Oh[(size_t)row0*HD_ + d]     = pack_h(o[nt][0]*inv0, o[nt][1]*inv0);
        *(uint32_t*)&Oh[(size_t)(row0+8)*HD_ + d] = pack_h(o[nt][2]*inv1, o[nt][3]*inv1);
    }
}

// ---------------------------------------------------------------------------
// Kernel 3: output projection — BK=64, 3-stage, single-pass fp16.
// ---------------------------------------------------------------------------
__global__ __launch_bounds__(256) void proj_mma(
    const float* __restrict__ bp, float* __restrict__ outp)
{
    extern __shared__ __half dynsm[];
    int tid = threadIdx.x, wid = tid >> 5, lane = tid & 31;
    int wm = wid >> 2, wn = wid & 3;
    const int m0 = blockIdx.x * 128, n0 = blockIdx.y * 128;

    uint32_t sbase = smem_u32(dynsm);
    uint32_t aoff = ((wm*64 + (lane & 15)) * SK + ((lane >> 4) << 3)) * 2;

    float acc[4][4][4] = {};

    auto fill = [&](int stage, int kc) {
        uint32_t st = sbase + stage*STAGE_H*2;
        int k0 = kc * BK;
        int h = k0 >> 6;
        #pragma unroll
        for (int it = 0; it < 8; it++) {
            int part = it >> 2;
            int idx = ((it & 3) << 8) + tid;
            int row = idx >> 3, seg = (idx & 7) << 3;
            if (part == 0) {
                int m = m0 + row, b_ = m >> 11, t = m & (T_-1);
                cp16(st + (row*SK + seg)*2,
                     g_oh + (((size_t)(b_*H_ + h))*T_ + t)*HD_ + seg);
            } else {
                cp16(st + (TILE_H + row*SK + seg)*2,
                     g_wpT + (size_t)(n0 + row)*C_ + k0 + seg);
            }
        }
    };

    fill(0, 0); CP_COMMIT();
    fill(1, 1); CP_COMMIT();

    for (int kc = 0; kc < 16; kc++) {
        CP_WAIT1();
        __syncthreads();
        if (kc + 2 < 16) fill((kc + 2) % 3, kc + 2);
        CP_COMMIT();
        gemm_mma_chunk(sbase + (kc % 3)*STAGE_H*2, aoff, wn, lane, acc);
    }

    #pragma unroll
    for (int mt = 0; mt < 4; mt++) {
        int mrow = m0 + wm*64 + mt*16 + (lane >> 2);
        #pragma unroll
        for (int half = 0; half < 2; half++) {
            int m = mrow + half*8;
            #pragma unroll
            for (int nt = 0; nt < 4; nt++) {
                int n = wn*32 + nt*8 + ((lane & 3) << 1);
                float c0 = acc[mt][nt][half*2+0] + bp[n0 + n];
                float c1 = acc[mt][nt][half*2+1] + bp[n0 + n + 1];
                *(float2*)&outp[(size_t)m*C_ + n0 + n] = make_float2(c0, c1);
            }
        }
    }
}

// ---------------------------------------------------------------------------
extern "C" void kernel_launch(void* const* d_in, const int* in_sizes, int n_in,
                              void* d_out, int out_size)
{
    const float* x  = (const float*)d_in[0];
    const float* Wq = (const float*)d_in[1];
    const float* bq = (const float*)d_in[2];
    const float* Wk = (const float*)d_in[3];
    const float* bk = (const float*)d_in[4];
    const float* Wv = (const float*)d_in[5];
    const float* bv = (const float*)d_in[6];
    const float* Wp = (const float*)d_in[7];
    const float* bp = (const float*)d_in[8];
    float* out = (float*)d_out;

    cudaFuncSetAttribute(qkv_mma,  cudaFuncAttributeMaxDynamicSharedMemorySize, GEMM_SMEM);
    cudaFuncSetAttribute(proj_mma, cudaFuncAttributeMaxDynamicSharedMemorySize, GEMM_SMEM);
    cudaFuncSetAttribute(attn_mma, cudaFuncAttributeMaxDynamicSharedMemorySize, ATTN_SMEM);

    conv_x<<<M_*C_/4/256, 256>>>(x, bq, bk, bv);
    conv_wT<<<4096, 256>>>(Wq, Wk, Wv, Wp);
    qkv_mma<<<dim3(64, 24), 256, GEMM_SMEM>>>();
    attn_mma<<<dim3(16, 64), 256, ATTN_SMEM>>>();
    proj_mma<<<dim3(64, 8), 256, GEMM_SMEM>>>(bp, out);
}

// round 16
// speedup vs baseline: 1.0829x; 1.0300x over previous
#include <cuda_runtime.h>
#include <cuda_fp16.h>
#include <math.h>
#include <stdint.h>

#define B_  4
#define T_  2048
#define C_  1024
#define H_  16
#define HD_ 64
#define M_  (B_*T_)   // 8192

// scale(1/32) * log2(e), folded into q at projection epilogue
#define QSC 0.045084213f

// fp16 scratch (allocation-free)
__device__ __half g_xh[M_*C_];
__device__ __half g_wqT[H_*HD_*C_], g_wkT[H_*HD_*C_], g_wvT[H_*HD_*C_];
__device__ __half g_wpT[C_*C_];
__device__ __half g_qh[M_*C_], g_kh[M_*C_], g_vh[M_*C_];
__device__ __half g_oh[M_*C_];
__device__ float  g_bias[3*H_*HD_];

// ---------------------------------------------------------------------------
// helpers
// ---------------------------------------------------------------------------
__device__ __forceinline__ uint32_t smem_u32(const void* p){
    uint32_t a;
    asm("{ .reg .u64 t; cvta.to.shared.u64 t, %1; cvt.u32.u64 %0, t; }"
        : "=r"(a) : "l"(p));
    return a;
}
__device__ __forceinline__ void ldsm_x4(uint32_t* r, uint32_t addr){
    asm volatile("ldmatrix.sync.aligned.m8n8.x4.shared.b16 {%0,%1,%2,%3}, [%4];"
        : "=r"(r[0]), "=r"(r[1]), "=r"(r[2]), "=r"(r[3]) : "r"(addr));
}
__device__ __forceinline__ void ldsm_x4t(uint32_t* r, uint32_t addr){
    asm volatile("ldmatrix.sync.aligned.m8n8.x4.trans.shared.b16 {%0,%1,%2,%3}, [%4];"
        : "=r"(r[0]), "=r"(r[1]), "=r"(r[2]), "=r"(r[3]) : "r"(addr));
}
__device__ __forceinline__ void mma16816(float* c, const uint32_t* a, const uint32_t* b){
    asm volatile(
        "mma.sync.aligned.m16n8k16.row.col.f32.f16.f16.f32 "
        "{%0,%1,%2,%3}, {%4,%5,%6,%7}, {%8,%9}, {%0,%1,%2,%3};"
        : "+f"(c[0]), "+f"(c[1]), "+f"(c[2]), "+f"(c[3])
        : "r"(a[0]), "r"(a[1]), "r"(a[2]), "r"(a[3]), "r"(b[0]), "r"(b[1]));
}
__device__ __forceinline__ void cp16(uint32_t dst, const void* src){
    asm volatile("cp.async.cg.shared.global [%0], [%1], 16;" :: "r"(dst), "l"(src));
}
#define CP_COMMIT() asm volatile("cp.async.commit_group;" ::: "memory")
#define CP_WAIT1()  asm volatile("cp.async.wait_group 1;" ::: "memory")

__device__ __forceinline__ uint32_t pack_h(float a, float b){
    __half2 hp = __floats2half2_rn(a, b);
    return *(uint32_t*)&hp;
}

// ---------------------------------------------------------------------------
// Prologue kernel 1: x -> fp16, + bias staging (blocks 0-3)
// ---------------------------------------------------------------------------
__global__ __launch_bounds__(256) void conv_x(
    const float* __restrict__ x,
    const float* __restrict__ bq, const float* __restrict__ bk,
    const float* __restrict__ bv)
{
    int gidx = blockIdx.x*256 + threadIdx.x;
    int i = gidx * 4;
    float4 a = *(const float4*)(x + i);
    uint2 hi;
    hi.x = pack_h(a.x, a.y);
    hi.y = pack_h(a.z, a.w);
    *(uint2*)&g_xh[i] = hi;
    if (gidx < H_*HD_) {
        g_bias[gidx]            = bq[gidx];
        g_bias[H_*HD_ + gidx]   = bk[gidx];
        g_bias[2*H_*HD_ + gidx] = bv[gidx];
    }
}

// ---------------------------------------------------------------------------
// Prologue kernel 2: coalesced weight transpose via 32x32 smem tiles.
// ---------------------------------------------------------------------------
__global__ __launch_bounds__(256) void conv_wT(
    const float* __restrict__ Wq, const float* __restrict__ Wk,
    const float* __restrict__ Wv, const float* __restrict__ Wp)
{
    __shared__ float ts[32][33];
    int tx = threadIdx.x & 31, ty = threadIdx.x >> 5;
    int bid = blockIdx.x;

    if (bid < 3072) {
        int which = bid >> 10;
        int r = bid & 1023;
        int h = r >> 6;
        int t = r & 63;
        int c0 = (t >> 1) << 5;
        int d0 = (t & 1) << 5;
        const float* W = (which == 0) ? Wq : (which == 1) ? Wk : Wv;
        __half* wT = (which == 0) ? g_wqT : (which == 1) ? g_wkT : g_wvT;
        #pragma unroll
        for (int i = 0; i < 4; i++) {
            int c = c0 + ty + i*8;
            ts[ty + i*8][tx] = W[((size_t)h*C_ + c)*HD_ + d0 + tx];
        }
        __syncthreads();
        #pragma unroll
        for (int i = 0; i < 4; i++) {
            int d = d0 + ty + i*8;
            wT[((size_t)h*HD_ + d)*C_ + c0 + tx] = __float2half_rn(ts[tx][ty + i*8]);
        }
    } else {
        int r = bid - 3072;
        int k0 = (r >> 5) << 5, n0 = (r & 31) << 5;
        #pragma unroll
        for (int i = 0; i < 4; i++) {
            int k = k0 + ty + i*8;
            ts[ty + i*8][tx] = Wp[(size_t)k*C_ + n0 + tx];
        }
        __syncthreads();
        #pragma unroll
        for (int i = 0; i < 4; i++) {
            int n = n0 + ty + i*8;
            g_wpT[(size_t)n*C_ + k0 + tx] = __float2half_rn(ts[tx][ty + i*8]);
        }
    }
}

// ---------------------------------------------------------------------------
// GEMM mma chunk: BK=64, single fp16 pass, paired-x4 B loads.
// ---------------------------------------------------------------------------
#define BK  64
#define SK  72
#define TILE_H (128*SK)
#define STAGE_H (2*TILE_H)
#define GEMM_SMEM (3*STAGE_H*2)   // 110592 B

__device__ __forceinline__ void gemm_mma_chunk(
    uint32_t st, uint32_t aoff, int wn, int lane, float acc[4][4][4])
{
    uint32_t sA = st, sB = st + TILE_H*2;
    int g01 = (lane >> 4) << 3;
    int gk  = ((lane >> 3) & 1) << 3;
    int l7  = lane & 7;

    #pragma unroll
    for (int ks = 0; ks < 4; ks++) {
        uint32_t bf[4][2];
        #pragma unroll
        for (int ntp = 0; ntp < 2; ntp++) {
            uint32_t tmp[4];
            uint32_t addr = sB + (((uint32_t)(wn*32 + ntp*16 + g01 + l7))*SK
                                  + ks*16 + gk)*2;
            ldsm_x4(tmp, addr);
            bf[2*ntp][0] = tmp[0]; bf[2*ntp][1] = tmp[1];
            bf[2*ntp+1][0] = tmp[2]; bf[2*ntp+1][1] = tmp[3];
        }
        uint32_t af[4][4];
        #pragma unroll
        for (int mt = 0; mt < 4; mt++)
            ldsm_x4(af[mt], sA + aoff + (mt*16*SK + ks*16)*2);
        #pragma unroll
        for (int mt = 0; mt < 4; mt++)
            #pragma unroll
            for (int nt = 0; nt < 4; nt++)
                mma16816(acc[mt][nt], af[mt], bf[nt]);
    }
}

// ---------------------------------------------------------------------------
// Kernel 1: QKV projection — BK=64, 3-stage, single-pass fp16.
//  q gets scale*log2e prefolded (after bias).
// ---------------------------------------------------------------------------
__global__ __launch_bounds__(256) void qkv_mma()
{
    extern __shared__ __half dynsm[];
    int tid = threadIdx.x, wid = tid >> 5, lane = tid & 31;
    int wm = wid >> 2, wn = wid & 3;
    int mt_ = blockIdx.x, nt_ = blockIdx.y;
    int which = nt_ >> 3, hbase = (nt_ & 7) * 2;
    const int m0 = mt_ * 128;

    const __half* wT = (which == 0) ? g_wqT : (which == 1) ? g_wkT : g_wvT;
    __half* outp = (which == 0) ? g_qh : (which == 1) ? g_kh : g_vh;
    const float osc = (which == 0) ? QSC : 1.0f;
    uint32_t sbase = smem_u32(dynsm);
    uint32_t aoff = ((wm*64 + (lane & 15)) * SK + ((lane >> 4) << 3)) * 2;

    float acc[4][4][4] = {};

    auto fill = [&](int stage, int kc) {
        uint32_t st = sbase + stage*STAGE_H*2;
        int k0 = kc * BK;
        #pragma unroll
        for (int it = 0; it < 8; it++) {
            int part = it >> 2;
            int idx = ((it & 3) << 8) + tid;
            int row = idx >> 3, seg = (idx & 7) << 3;
            if (part == 0) {
                cp16(st + (row*SK + seg)*2,
                     g_xh + (size_t)(m0 + row)*C_ + k0 + seg);
            } else {
                int h = hbase + (row >> 6), d = row & 63;
                cp16(st + (TILE_H + row*SK + seg)*2,
                     wT + ((size_t)h*HD_ + d)*C_ + k0 + seg);
            }
        }
    };

    fill(0, 0); CP_COMMIT();
    fill(1, 1); CP_COMMIT();

    for (int kc = 0; kc < 16; kc++) {
        CP_WAIT1();
        __syncthreads();
        if (kc + 2 < 16) fill((kc + 2) % 3, kc + 2);
        CP_COMMIT();
        gemm_mma_chunk(sbase + (kc % 3)*STAGE_H*2, aoff, wn, lane, acc);
    }

    #pragma unroll
    for (int mt = 0; mt < 4; mt++) {
        int mrow = m0 + wm*64 + mt*16 + (lane >> 2);
        #pragma unroll
        for (int half = 0; half < 2; half++) {
            int m = mrow + half*8;
            int b_ = m >> 11, t = m & (T_-1);
            #pragma unroll
            for (int nt = 0; nt < 4; nt++) {
                int n = wn*32 + nt*8 + ((lane & 3) << 1);
                int h = hbase + (n >> 6), d = n & 63;
                size_t off = (((size_t)(b_*H_ + h))*T_ + t)*HD_ + d;
                float c0 = (acc[mt][nt][half*2+0] + g_bias[(which*H_ + h)*HD_ + d]) * osc;
                float c1 = (acc[mt][nt][half*2+1] + g_bias[(which*H_ + h)*HD_ + d + 1]) * osc;
                *(uint32_t*)&outp[off] = pack_h(c0, c1);
            }
        }
    }
}

// ---------------------------------------------------------------------------
// Kernel 2: attention — 64-key tiles, log2-domain softmax.
// ---------------------------------------------------------------------------
#define SKA 72
#define ATILE_H (64*SKA)
#define ASTAGE_H (2*ATILE_H)
#define ATTN_SMEM (3*ASTAGE_H*2)   // 55296 B

__global__ __launch_bounds__(256) void attn_mma()
{
    extern __shared__ __half asm_[];
    int tid = threadIdx.x, wid = tid >> 5, lane = tid & 31;
    int qt = 15 - blockIdx.x;
    int bh = blockIdx.y;
    const __half* Qh = g_qh + (size_t)bh * T_ * HD_;
    const __half* Kh = g_kh + (size_t)bh * T_ * HD_;
    const __half* Vh = g_vh + (size_t)bh * T_ * HD_;

    uint32_t sbase = smem_u32(asm_);
    int r0 = lane >> 2, c0 = (lane & 3) << 1;
    int wrow = qt*128 + wid*16;
    int row0 = wrow + r0;
    int g01 = (lane >> 4) << 3;
    int gk  = ((lane >> 3) & 1) << 3;
    int l7  = lane & 7;

    uint32_t qh[4][4];
    #pragma unroll
    for (int ks = 0; ks < 4; ks++) {
        #pragma unroll
        for (int p = 0; p < 4; p++) {
            int rr = row0 + ((p & 1) << 3);
            int cc = ks*16 + c0 + ((p >> 1) << 3);
            qh[ks][p] = *(const uint32_t*)&Qh[(size_t)rr*HD_ + cc];
        }
    }

    float o[8][4];
    #pragma unroll
    for (int i = 0; i < 8; i++) { o[i][0]=o[i][1]=o[i][2]=o[i][3]=0.f; }
    float m_i[2] = {-1e30f, -1e30f}, l_i[2] = {0.f, 0.f};
    int jmax = 2*qt + 1;

    auto fill = [&](int stage, int j) {
        uint32_t st = sbase + stage*ASTAGE_H*2;
        int s0 = j * 64;
        #pragma unroll
        for (int it = 0; it < 4; it++) {
            int part = it >> 1;
            int idx = ((it & 1) << 8) + tid;
            int row = idx >> 3, seg = (idx & 7) << 3;
            if (part == 0)
                cp16(st + (row*SKA + seg)*2, Kh + (size_t)(s0 + row)*HD_ + seg);
            else
                cp16(st + (ATILE_H + row*SKA + seg)*2, Vh + (size_t)(s0 + row)*HD_ + seg);
        }
    };

    fill(0, 0); CP_COMMIT();
    fill(1, 1); CP_COMMIT();

    for (int j = 0; j <= jmax; j++) {
        CP_WAIT1();
        __syncthreads();
        if (j + 2 <= jmax) fill((j + 2) % 3, j + 2);
        CP_COMMIT();

        bool dead = (j*64) > (wrow + 15);
        if (!dead) {
            uint32_t st = sbase + (j % 3)*ASTAGE_H*2;
            uint32_t sK = st, sV = st + ATILE_H*2;
            // S' = (log2e*scale*Q) K^T  — scale already in Q
            float c[8][4] = {};
            #pragma unroll
            for (int ks = 0; ks < 4; ks++) {
                uint32_t bf[8][2];
                #pragma unroll
                for (int ntp = 0; ntp < 4; ntp++) {
                    uint32_t tmp[4];
                    uint32_t addr = sK + (((uint32_t)(ntp*16 + g01 + l7))*SKA
                                          + ks*16 + gk)*2;
                    ldsm_x4(tmp, addr);
                    bf[2*ntp][0] = tmp[0]; bf[2*ntp][1] = tmp[1];
                    bf[2*ntp+1][0] = tmp[2]; bf[2*ntp+1][1] = tmp[3];
                }
                #pragma unroll
                for (int nt = 0; nt < 8; nt++)
                    mma16816(c[nt], qh[ks], bf[nt]);
            }
            // causal mask (diag tiles only); no scale multiply needed
            if (j >= 2*qt) {
                #pragma unroll
                for (int nt = 0; nt < 8; nt++) {
                    #pragma unroll
                    for (int e = 0; e < 4; e++) {
                        int col = j*64 + nt*8 + c0 + (e & 1);
                        int row = row0 + ((e >> 1) << 3);
                        if (col > row) c[nt][e] = -1e30f;
                    }
                }
            }
            // online softmax in log2 domain
            #pragma unroll
            for (int r = 0; r < 2; r++) {
                float mx = -1e30f;
                #pragma unroll
                for (int nt = 0; nt < 8; nt++)
                    mx = fmaxf(mx, fmaxf(c[nt][2*r], c[nt][2*r+1]));
                mx = fmaxf(mx, __shfl_xor_sync(0xffffffffu, mx, 1));
                mx = fmaxf(mx, __shfl_xor_sync(0xffffffffu, mx, 2));
                float mnew = fmaxf(m_i[r], mx);
                float alpha = exp2f(m_i[r] - mnew);
                m_i[r] = mnew;
                float rs = 0.f;
                #pragma unroll
                for (int nt = 0; nt < 8; nt++) {
                    float p0 = exp2f(c[nt][2*r]   - mnew);
                    float p1 = exp2f(c[nt][2*r+1] - mnew);
                    c[nt][2*r] = p0; c[nt][2*r+1] = p1;
                    rs += p0 + p1;
                }
                rs += __shfl_xor_sync(0xffffffffu, rs, 1);
                rs += __shfl_xor_sync(0xffffffffu, rs, 2);
                l_i[r] = l_i[r]*alpha + rs;
                #pragma unroll
                for (int nt = 0; nt < 8; nt++) {
                    o[nt][2*r]   *= alpha;
                    o[nt][2*r+1] *= alpha;
                }
            }
            // O += P V
            #pragma unroll
            for (int ks = 0; ks < 4; ks++) {
                uint32_t ph[4];
                ph[0] = pack_h(c[2*ks][0],   c[2*ks][1]);
                ph[1] = pack_h(c[2*ks][2],   c[2*ks][3]);
                ph[2] = pack_h(c[2*ks+1][0], c[2*ks+1][1]);
                ph[3] = pack_h(c[2*ks+1][2], c[2*ks+1][3]);
                uint32_t bv[8][2];
                #pragma unroll
                for (int ntp = 0; ntp < 4; ntp++) {
                    uint32_t tmp[4];
                    uint32_t addr = sV + (((uint32_t)(ks*16 + gk + l7))*SKA
                                          + ntp*16 + g01)*2;
                    ldsm_x4t(tmp, addr);
                    bv[2*ntp][0] = tmp[0]; bv[2*ntp][1] = tmp[1];
                    bv[2*ntp+1][0] = tmp[2]; bv[2*ntp+1][1] = tmp[3];
                }
                #pragma unroll
                for (int nt = 0; nt < 8; nt++)
                    mma16816(o[nt], ph, bv[nt]);
            }
        }
        __syncthreads();
    }

    float inv0 = 1.0f / l_i[0], inv1 = 1.0f / l_i[1];
    __half* Oh = g_oh + (size_t)bh * T_ * HD_;
    #pragma unroll
    for (int nt = 0; nt < 8; nt++) {
        int d = nt*8 + c0;
        *(uint32_t*)&Oh[(size_t)row0*HD_ + d]     = pack_h(o[nt][0]*inv0, o[nt][1]*inv0);
        *(uint32_t*)&Oh[(size_t)(row0+8)*HD_ + d] = pack_h(o[nt][2]*inv1, o[nt][3]*inv1);
    }
}

// ---------------------------------------------------------------------------
// Kernel 3: output projection — BK=64, 3-stage, single-pass fp16.
// ---------------------------------------------------------------------------
__global__ __launch_bounds__(256) void proj_mma(
    const float* __restrict__ bp, float* __restrict__ outp)
{
    extern __shared__ __half dynsm[];
    int tid = threadIdx.x, wid = tid >> 5, lane = tid & 31;
    int wm = wid >> 2, wn = wid & 3;
    const int m0 = blockIdx.x * 128, n0 = blockIdx.y * 128;

    uint32_t sbase = smem_u32(dynsm);
    uint32_t aoff = ((wm*64 + (lane & 15)) * SK + ((lane >> 4) << 3)) * 2;

    float acc[4][4][4] = {};

    auto fill = [&](int stage, int kc) {
        uint32_t st = sbase + stage*STAGE_H*2;
        int k0 = kc * BK;
        int h = k0 >> 6;
        #pragma unroll
        for (int it = 0; it < 8; it++) {
            int part = it >> 2;
            int idx = ((it & 3) << 8) + tid;
            int row = idx >> 3, seg = (idx & 7) << 3;
            if (part == 0) {
                int m = m0 + row, b_ = m >> 11, t = m & (T_-1);
                cp16(st + (row*SK + seg)*2,
                     g_oh + (((size_t)(b_*H_ + h))*T_ + t)*HD_ + seg);
            } else {
                cp16(st + (TILE_H + row*SK + seg)*2,
                     g_wpT + (size_t)(n0 + row)*C_ + k0 + seg);
            }
        }
    };

    fill(0, 0); CP_COMMIT();
    fill(1, 1); CP_COMMIT();

    for (int kc = 0; kc < 16; kc++) {
        CP_WAIT1();
        __syncthreads();
        if (kc + 2 < 16) fill((kc + 2) % 3, kc + 2);
        CP_COMMIT();
        gemm_mma_chunk(sbase + (kc % 3)*STAGE_H*2, aoff, wn, lane, acc);
    }

    #pragma unroll
    for (int mt = 0; mt < 4; mt++) {
        int mrow = m0 + wm*64 + mt*16 + (lane >> 2);
        #pragma unroll
        for (int half = 0; half < 2; half++) {
            int m = mrow + half*8;
            #pragma unroll
            for (int nt = 0; nt < 4; nt++) {
                int n = wn*32 + nt*8 + ((lane & 3) << 1);
                float c0 = acc[mt][nt][half*2+0] + bp[n0 + n];
                float c1 = acc[mt][nt][half*2+1] + bp[n0 + n + 1];
                *(float2*)&outp[(size_t)m*C_ + n0 + n] = make_float2(c0, c1);
            }
        }
    }
}

// ---------------------------------------------------------------------------
extern "C" void kernel_launch(void* const* d_in, const int* in_sizes, int n_in,
                              void* d_out, int out_size)
{
    const float* x  = (const float*)d_in[0];
    const float* Wq = (const float*)d_in[1];
    const float* bq = (const float*)d_in[2];
    const float* Wk = (const float*)d_in[3];
    const float* bk = (const float*)d_in[4];
    const float* Wv = (const float*)d_in[5];
    const float* bv = (const float*)d_in[6];
    const float* Wp = (const float*)d_in[7];
    const float* bp = (const float*)d_in[8];
    float* out = (float*)d_out;

    cudaFuncSetAttribute(qkv_mma,  cudaFuncAttributeMaxDynamicSharedMemorySize, GEMM_SMEM);
    cudaFuncSetAttribute(proj_mma, cudaFuncAttributeMaxDynamicSharedMemorySize, GEMM_SMEM);
    cudaFuncSetAttribute(attn_mma, cudaFuncAttributeMaxDynamicSharedMemorySize, ATTN_SMEM);

    conv_x<<<M_*C_/4/256, 256>>>(x, bq, bk, bv);
    conv_wT<<<4096, 256>>>(Wq, Wk, Wv, Wp);
    qkv_mma<<<dim3(64, 24), 256, GEMM_SMEM>>>();
    attn_mma<<<dim3(16, 64), 256, ATTN_SMEM>>>();
    proj_mma<<<dim3(64, 8), 256, GEMM_SMEM>>>(bp, out);
}